// round 1
// baseline (speedup 1.0000x reference)
#include <cuda_runtime.h>

#define N_NODES 20000
#define N_EDGES 320000

// ---------------- device scratch (allocation-free rule: __device__ globals) ----
__device__ float g_h[N_NODES * 64];                 //   5.1 MB  h = nf@w_up * 1/8
__device__ float g_mix[(size_t)N_EDGES * 192];      // 245.8 MB  MLP output per edge
__device__ float g_agg[(size_t)N_NODES * 576];      //  46.1 MB  scattered messages

// ---------------- kernel 0: zero the aggregation buffer -----------------------
__global__ void k_zero() {
    size_t i = (size_t)blockIdx.x * 256 + threadIdx.x;   // grid covers exactly 2.88M float4
    reinterpret_cast<float4*>(g_agg)[i] = make_float4(0.f, 0.f, 0.f, 0.f);
}

// ---------------- kernel 1: h = node_feats @ w_up * (1/sqrt(C)) ---------------
__global__ void __launch_bounds__(256) k_node_up(const float* __restrict__ nf,
                                                 const float* __restrict__ w) {
    __shared__ __align__(16) float sW[64 * 64];
    __shared__ float sA[32 * 65];
    const int t  = threadIdx.x;
    const int nb = blockIdx.x * 32;

    for (int i = t; i < 4096; i += 256) sW[i] = w[i];
    for (int i = t; i < 2048; i += 256) sA[(i >> 6) * 65 + (i & 63)] = nf[nb * 64 + i];
    __syncthreads();

    const int ty = t >> 4, tx = t & 15;
    const int r0 = ty * 2, c0 = tx * 4;
    float acc[2][4] = {};
#pragma unroll 8
    for (int k = 0; k < 64; k++) {
        float a0 = sA[r0 * 65 + k];
        float a1 = sA[(r0 + 1) * 65 + k];
        float4 b = *reinterpret_cast<const float4*>(&sW[k * 64 + c0]);
        acc[0][0] += a0 * b.x; acc[0][1] += a0 * b.y; acc[0][2] += a0 * b.z; acc[0][3] += a0 * b.w;
        acc[1][0] += a1 * b.x; acc[1][1] += a1 * b.y; acc[1][2] += a1 * b.z; acc[1][3] += a1 * b.w;
    }
#pragma unroll
    for (int i = 0; i < 2; i++)
#pragma unroll
        for (int j = 0; j < 4; j++)
            g_h[(nb + r0 + i) * 64 + c0 + j] = acc[i][j] * 0.125f;
}

// ---------------- kernel 2: fused 4-layer edge MLP ----------------------------
__device__ __forceinline__ float silu_f(float x) { return x / (1.f + __expf(-x)); }

// O[e][j] = act( (A[e][:] @ W)[j] * scale ), A row-stride 65 (bank-conflict pad)
__device__ __forceinline__ void gemm_tile64(const float* __restrict__ A,
                                            const float* __restrict__ W,
                                            float* __restrict__ O,
                                            int e0, int j0, float scale) {
    float acc[4][8];
#pragma unroll
    for (int i = 0; i < 4; i++)
#pragma unroll
        for (int j = 0; j < 8; j++) acc[i][j] = 0.f;

#pragma unroll 8
    for (int k = 0; k < 64; k++) {
        float a[4];
#pragma unroll
        for (int i = 0; i < 4; i++) a[i] = A[(e0 + i) * 65 + k];
#pragma unroll
        for (int jc = 0; jc < 2; jc++) {
            float4 b = *reinterpret_cast<const float4*>(&W[k * 64 + j0 + jc * 4]);
#pragma unroll
            for (int i = 0; i < 4; i++) {
                acc[i][jc * 4 + 0] += a[i] * b.x;
                acc[i][jc * 4 + 1] += a[i] * b.y;
                acc[i][jc * 4 + 2] += a[i] * b.z;
                acc[i][jc * 4 + 3] += a[i] * b.w;
            }
        }
    }
#pragma unroll
    for (int i = 0; i < 4; i++)
#pragma unroll
        for (int j = 0; j < 8; j++)
            O[(e0 + i) * 65 + j0 + j] = silu_f(acc[i][j] * scale);
}

__global__ void __launch_bounds__(256) k_mlp(const float* __restrict__ radial,
                                             const float* __restrict__ w1,
                                             const float* __restrict__ w2,
                                             const float* __restrict__ w3,
                                             const float* __restrict__ w4) {
    extern __shared__ float sm[];
    float* sW1 = sm;              //   512
    float* sW2 = sW1 + 512;       //  4096
    float* sW3 = sW2 + 4096;      //  4096
    float* sW4 = sW3 + 4096;      // 12288
    float* sR  = sW4 + 12288;     // 128*9
    float* sA  = sR + 1152;       // 128*65
    float* sB  = sA + 8320;       // 128*65   (total 38784 floats = 155136 B)

    const int t  = threadIdx.x;
    const size_t eb = (size_t)blockIdx.x * 128;

    for (int i = t; i < 512;   i += 256) sW1[i] = w1[i];
    for (int i = t; i < 4096;  i += 256) sW2[i] = w2[i];
    for (int i = t; i < 4096;  i += 256) sW3[i] = w3[i];
    for (int i = t; i < 12288; i += 256) sW4[i] = w4[i];
    for (int i = t; i < 1024;  i += 256) sR[(i >> 3) * 9 + (i & 7)] = radial[eb * 8 + i];
    __syncthreads();

    const int ty = t >> 3, tx = t & 7;
    const int e0 = ty * 4, j0 = tx * 8;

    // ---- layer 1: [128,8] @ [8,64], scale 1/sqrt(8), silu ----
    {
        float acc[4][8] = {};
#pragma unroll
        for (int k = 0; k < 8; k++) {
            float a[4];
#pragma unroll
            for (int i = 0; i < 4; i++) a[i] = sR[(e0 + i) * 9 + k];
#pragma unroll
            for (int jc = 0; jc < 2; jc++) {
                float4 b = *reinterpret_cast<const float4*>(&sW1[k * 64 + j0 + jc * 4]);
#pragma unroll
                for (int i = 0; i < 4; i++) {
                    acc[i][jc * 4 + 0] += a[i] * b.x;
                    acc[i][jc * 4 + 1] += a[i] * b.y;
                    acc[i][jc * 4 + 2] += a[i] * b.z;
                    acc[i][jc * 4 + 3] += a[i] * b.w;
                }
            }
        }
        const float sc = 0.35355339059327373f;
#pragma unroll
        for (int i = 0; i < 4; i++)
#pragma unroll
            for (int j = 0; j < 8; j++)
                sA[(e0 + i) * 65 + j0 + j] = silu_f(acc[i][j] * sc);
    }
    __syncthreads();

    // ---- layer 2 & 3: [128,64] @ [64,64], scale 1/8, silu ----
    gemm_tile64(sA, sW2, sB, e0, j0, 0.125f);
    __syncthreads();
    gemm_tile64(sB, sW3, sA, e0, j0, 0.125f);
    __syncthreads();

    // ---- layer 4: [128,64] @ [64,192], scale 1/8, NO activation -> global ----
    {
        const int j4 = tx * 24;
        float acc[4][24];
#pragma unroll
        for (int i = 0; i < 4; i++)
#pragma unroll
            for (int j = 0; j < 24; j++) acc[i][j] = 0.f;

#pragma unroll 4
        for (int k = 0; k < 64; k++) {
            float a[4];
#pragma unroll
            for (int i = 0; i < 4; i++) a[i] = sA[(e0 + i) * 65 + k];
#pragma unroll
            for (int jc = 0; jc < 6; jc++) {
                float4 b = *reinterpret_cast<const float4*>(&sW4[k * 192 + j4 + jc * 4]);
#pragma unroll
                for (int i = 0; i < 4; i++) {
                    acc[i][jc * 4 + 0] += a[i] * b.x;
                    acc[i][jc * 4 + 1] += a[i] * b.y;
                    acc[i][jc * 4 + 2] += a[i] * b.z;
                    acc[i][jc * 4 + 3] += a[i] * b.w;
                }
            }
        }
#pragma unroll
        for (int i = 0; i < 4; i++) {
            size_t row = (eb + e0 + i) * 192;
#pragma unroll
            for (int jc = 0; jc < 6; jc++) {
                float4 o;
                o.x = acc[i][jc * 4 + 0] * 0.125f;
                o.y = acc[i][jc * 4 + 1] * 0.125f;
                o.z = acc[i][jc * 4 + 2] * 0.125f;
                o.w = acc[i][jc * 4 + 3] * 0.125f;
                *reinterpret_cast<float4*>(&g_mix[row + j4 + jc * 4]) = o;
            }
        }
    }
}

// ---------------- kernel 3: per-edge message + atomic scatter -----------------
__global__ void __launch_bounds__(256) k_scatter(const float* __restrict__ vectors,
                                                 const int* __restrict__ senders,
                                                 const int* __restrict__ receivers) {
    const int e    = blockIdx.x * 8 + (threadIdx.x >> 5);   // warp per edge
    const int lane = threadIdx.x & 31;

    const int r = receivers[e];
    const int s = senders[e];

    float vx = vectors[e * 3 + 0], vy = vectors[e * 3 + 1], vz = vectors[e * 3 + 2];
    float rn = rsqrtf(vx * vx + vy * vy + vz * vz);
    float x = vx * rn, y = vy * rn, z = vz * rn;

    const float SQ3 = 1.7320508075688772f;    // sqrt(3)
    const float S15 = 3.872983346207417f;     // sqrt(15)
    float y1[3] = { SQ3 * x, SQ3 * y, SQ3 * z };
    float y2[5] = { S15 * x * y, S15 * y * z,
                    1.118033988749895f * (3.f * z * z - 1.f),   // 0.5*sqrt(5)
                    S15 * x * z, 0.5f * S15 * (x * x - y * y) };

    const float SC = 1.0f / 128.0f;           // (1/C) * EPS folded
    const float* hrow = g_h   + (size_t)s * 64;
    const float* mrow = g_mix + (size_t)e * 192;
    float*       base = g_agg + (size_t)r * 576;

#pragma unroll
    for (int half = 0; half < 2; half++) {
        int c = lane + half * 32;
        float sv = hrow[c];
        float t0 = sv * mrow[c]       * SC;
        float t1 = sv * mrow[64 + c]  * SC;
        float t2 = sv * mrow[128 + c] * SC;
        atomicAdd(base + c, t0);                                  // l=0, coalesced
#pragma unroll
        for (int m = 0; m < 3; m++) atomicAdd(base + 64  + c * 3 + m, t1 * y1[m]);
#pragma unroll
        for (int m = 0; m < 5; m++) atomicAdd(base + 256 + c * 5 + m, t2 * y2[m]);
    }
}

// ---------------- kernel 4: 9 strided GEMMs for the down-projection -----------
__global__ void __launch_bounds__(256) k_down(const float* __restrict__ w0,
                                              const float* __restrict__ w1,
                                              const float* __restrict__ w2,
                                              float* __restrict__ out) {
    __shared__ __align__(16) float sW[64 * 64];
    __shared__ float sA[64 * 65];

    const int seg = blockIdx.y;
    const float* W; int off, stride;
    if (seg == 0)      { W = w0; off = 0;                 stride = 1; }
    else if (seg < 4)  { W = w1; off = 64  + (seg - 1);   stride = 3; }
    else               { W = w2; off = 256 + (seg - 4);   stride = 5; }

    const int t  = threadIdx.x;
    const int nb = blockIdx.x * 64;

    for (int i = t; i < 4096; i += 256) sW[i] = W[i];
    for (int i = t; i < 4096; i += 256) {
        int rr = i >> 6, cc = i & 63;
        int n = nb + rr;
        sA[rr * 65 + cc] = (n < N_NODES) ? g_agg[(size_t)n * 576 + off + cc * stride] : 0.f;
    }
    __syncthreads();

    const int ty = t >> 4, tx = t & 15;
    const int r0 = ty * 4, d0 = tx * 4;
    float acc[4][4] = {};
#pragma unroll 8
    for (int k = 0; k < 64; k++) {
        float a[4];
#pragma unroll
        for (int i = 0; i < 4; i++) a[i] = sA[(r0 + i) * 65 + k];
        float4 b = *reinterpret_cast<const float4*>(&sW[k * 64 + d0]);
#pragma unroll
        for (int i = 0; i < 4; i++) {
            acc[i][0] += a[i] * b.x;
            acc[i][1] += a[i] * b.y;
            acc[i][2] += a[i] * b.z;
            acc[i][3] += a[i] * b.w;
        }
    }
#pragma unroll
    for (int i = 0; i < 4; i++) {
        int n = nb + r0 + i;
        if (n < N_NODES) {
#pragma unroll
            for (int j = 0; j < 4; j++)
                out[(size_t)n * 576 + off + (size_t)(d0 + j) * stride] = acc[i][j] * 0.125f;
        }
    }
}

// ---------------- launcher ----------------------------------------------------
extern "C" void kernel_launch(void* const* d_in, const int* in_sizes, int n_in,
                              void* d_out, int out_size) {
    const float* vectors    = (const float*)d_in[0];
    const float* node_feats = (const float*)d_in[1];
    const float* radial     = (const float*)d_in[2];
    const int*   senders    = (const int*)  d_in[3];
    const int*   receivers  = (const int*)  d_in[4];
    const float* w_up       = (const float*)d_in[5];
    const float* mlp_w1     = (const float*)d_in[6];
    const float* mlp_w2     = (const float*)d_in[7];
    const float* mlp_w3     = (const float*)d_in[8];
    const float* mlp_w4     = (const float*)d_in[9];
    const float* w_down0    = (const float*)d_in[10];
    const float* w_down1    = (const float*)d_in[11];
    const float* w_down2    = (const float*)d_in[12];
    float* out = (float*)d_out;

    const int MLP_SMEM = 38784 * 4;   // 155136 B dynamic smem
    cudaFuncSetAttribute(k_mlp, cudaFuncAttributeMaxDynamicSharedMemorySize, MLP_SMEM);

    k_zero<<<11250, 256>>>();                                     // 20000*576 = 11250*256*4
    k_node_up<<<625, 256>>>(node_feats, w_up);                    // 20000 = 625*32
    k_mlp<<<2500, 256, MLP_SMEM>>>(radial, mlp_w1, mlp_w2, mlp_w3, mlp_w4);  // 320000 = 2500*128
    k_scatter<<<40000, 256>>>(vectors, senders, receivers);       // 320000 = 40000*8 warps
    k_down<<<dim3(313, 9), 256>>>(w_down0, w_down1, w_down2, out);
}

// round 2
// speedup vs baseline: 1.3297x; 1.3297x over previous
#include <cuda_runtime.h>

#define N_NODES 20000
#define N_EDGES 320000

typedef unsigned long long u64;

// ---------------- device scratch (allocation-free rule) -----------------------
__device__ __align__(16) float g_h[N_NODES * 64];              // 5.1 MB, h = nf@w_up/8
__device__ __align__(16) float g_agg[(size_t)N_NODES * 576];   // 46 MB, m-major planes

// ---------------- packed fp32x2 + vector-red helpers --------------------------
__device__ __forceinline__ u64 pack2(float x, float y) {
    u64 r; asm("mov.b64 %0, {%1, %2};" : "=l"(r) : "f"(x), "f"(y)); return r;
}
__device__ __forceinline__ void unpack2(u64 v, float& x, float& y) {
    asm("mov.b64 {%0, %1}, %2;" : "=f"(x), "=f"(y) : "l"(v));
}
__device__ __forceinline__ u64 fma2(u64 a, u64 b, u64 c) {
    u64 d; asm("fma.rn.f32x2 %0, %1, %2, %3;" : "=l"(d) : "l"(a), "l"(b), "l"(c)); return d;
}
__device__ __forceinline__ void red4(float* p, float a, float b, float c, float d) {
    asm volatile("red.global.add.v4.f32 [%0], {%1, %2, %3, %4};"
                 :: "l"((u64)__cvta_generic_to_global(p)),
                    "f"(a), "f"(b), "f"(c), "f"(d) : "memory");
}

// ---------------- kernel 0: zero the aggregation buffer -----------------------
__global__ void k_zero() {
    size_t i = (size_t)blockIdx.x * 256 + threadIdx.x;   // 2.88M float4 exactly
    reinterpret_cast<float4*>(g_agg)[i] = make_float4(0.f, 0.f, 0.f, 0.f);
}

// ---------------- kernel 1: h = node_feats @ w_up * (1/8) ---------------------
__global__ void __launch_bounds__(256) k_node_up(const float* __restrict__ nf,
                                                 const float* __restrict__ w) {
    __shared__ __align__(16) float sW[64 * 64];
    __shared__ float sA[32 * 65];
    const int t  = threadIdx.x;
    const int nb = blockIdx.x * 32;

    for (int i = t; i < 4096; i += 256) sW[i] = w[i];
    for (int i = t; i < 2048; i += 256) sA[(i >> 6) * 65 + (i & 63)] = nf[nb * 64 + i];
    __syncthreads();

    const int ty = t >> 4, tx = t & 15;
    const int r0 = ty * 2, c0 = tx * 4;
    float acc[2][4] = {};
#pragma unroll 8
    for (int k = 0; k < 64; k++) {
        float a0 = sA[r0 * 65 + k];
        float a1 = sA[(r0 + 1) * 65 + k];
        float4 b = *reinterpret_cast<const float4*>(&sW[k * 64 + c0]);
        acc[0][0] += a0 * b.x; acc[0][1] += a0 * b.y; acc[0][2] += a0 * b.z; acc[0][3] += a0 * b.w;
        acc[1][0] += a1 * b.x; acc[1][1] += a1 * b.y; acc[1][2] += a1 * b.z; acc[1][3] += a1 * b.w;
    }
#pragma unroll
    for (int i = 0; i < 2; i++)
#pragma unroll
        for (int j = 0; j < 4; j++)
            g_h[(nb + r0 + i) * 64 + c0 + j] = acc[i][j] * 0.125f;
}

// ---------------- fused MLP + message + scatter --------------------------------
// Edge-per-thread. Activations in smem columns [64][257] (thread t owns column t,
// conflict-free, no cross-thread sharing -> no syncs). Weights smem-resident.
// Aggregation buffer is m-major: [0:64) l0, [64+p*64+c) p<3 l1, [256+p*64+c) p<5 l2.

__device__ __forceinline__ void layer64(const float* __restrict__ sW,
                                        const float* __restrict__ sIn,
                                        float* __restrict__ sOut,
                                        int t, float scale) {
    u64 acc[32];
#pragma unroll
    for (int j = 0; j < 32; j++) acc[j] = 0ull;
    const ulonglong2* Wv = reinterpret_cast<const ulonglong2*>(sW);
#pragma unroll 4
    for (int k = 0; k < 64; k++) {
        float av = sIn[k * 257 + t];
        u64 a2 = pack2(av, av);
        const ulonglong2* row = Wv + k * 16;
#pragma unroll
        for (int j = 0; j < 16; j++) {
            ulonglong2 w = row[j];
            acc[2 * j]     = fma2(a2, w.x, acc[2 * j]);
            acc[2 * j + 1] = fma2(a2, w.y, acc[2 * j + 1]);
        }
    }
#pragma unroll
    for (int j = 0; j < 32; j++) {
        float x, y; unpack2(acc[j], x, y);
        x *= scale; y *= scale;
        sOut[(2 * j) * 257 + t]     = x / (1.f + __expf(-x));
        sOut[(2 * j + 1) * 257 + t] = y / (1.f + __expf(-y));
    }
}

template <int L>
__device__ __forceinline__ void segment(const float* __restrict__ sW4,
                                        const float* __restrict__ sIn, int t,
                                        const float* __restrict__ hrow,
                                        float* __restrict__ aggbase,
                                        const float* __restrict__ Y) {
    constexpr int NP  = (L == 0) ? 1 : (L == 1 ? 3 : 5);
    constexpr int OFF = (L == 0) ? 0 : (L == 1 ? 64 : 256);
    u64 acc[32];
#pragma unroll
    for (int j = 0; j < 32; j++) acc[j] = 0ull;
    const ulonglong2* Wv = reinterpret_cast<const ulonglong2*>(sW4);
#pragma unroll 4
    for (int k = 0; k < 64; k++) {
        float av = sIn[k * 257 + t];
        u64 a2 = pack2(av, av);
        const ulonglong2* row = Wv + k * 48 + L * 16;   // 192-col row = 48 ulonglong2
#pragma unroll
        for (int j = 0; j < 16; j++) {
            ulonglong2 w = row[j];
            acc[2 * j]     = fma2(a2, w.x, acc[2 * j]);
            acc[2 * j + 1] = fma2(a2, w.y, acc[2 * j + 1]);
        }
    }
    const float SCL = 0.0009765625f;   // 0.125 (w4 norm) * (1/64) * 0.5 (EPS)
#pragma unroll
    for (int c4 = 0; c4 < 16; c4++) {
        float f0, f1, f2, f3;
        unpack2(acc[2 * c4],     f0, f1);
        unpack2(acc[2 * c4 + 1], f2, f3);
        float4 h4 = *reinterpret_cast<const float4*>(hrow + c4 * 4);
        float u0 = f0 * h4.x * SCL;
        float u1 = f1 * h4.y * SCL;
        float u2 = f2 * h4.z * SCL;
        float u3 = f3 * h4.w * SCL;
#pragma unroll
        for (int p = 0; p < NP; p++) {
            float yp = Y[p];
            red4(aggbase + OFF + p * 64 + c4 * 4, u0 * yp, u1 * yp, u2 * yp, u3 * yp);
        }
    }
}

__global__ void __launch_bounds__(256) k_fused(
    const float* __restrict__ radial, const float* __restrict__ vectors,
    const int* __restrict__ senders, const int* __restrict__ receivers,
    const float* __restrict__ w1, const float* __restrict__ w2,
    const float* __restrict__ w3, const float* __restrict__ w4) {
    extern __shared__ float sm[];
    float* sW1 = sm;              //   512
    float* sW2 = sm + 512;        //  4096
    float* sW3 = sm + 4608;       //  4096
    float* sW4 = sm + 8704;       // 12288
    float* sA  = sm + 20992;      // 64*257
    float* sB  = sm + 37440;      // 64*257  (total 53888 floats = 215552 B)
    const int t = threadIdx.x;

    {   // cooperative weight load
        const float4* s1 = (const float4*)w1; float4* d1 = (float4*)sW1;
        for (int i = t; i < 128;  i += 256) d1[i] = s1[i];
        const float4* s2 = (const float4*)w2; float4* d2 = (float4*)sW2;
        for (int i = t; i < 1024; i += 256) d2[i] = s2[i];
        const float4* s3 = (const float4*)w3; float4* d3 = (float4*)sW3;
        for (int i = t; i < 1024; i += 256) d3[i] = s3[i];
        const float4* s4 = (const float4*)w4; float4* d4 = (float4*)sW4;
        for (int i = t; i < 3072; i += 256) d4[i] = s4[i];
    }
    __syncthreads();

    const int e = blockIdx.x * 256 + t;         // 1250*256 = 320000 exactly
    const int s = senders[e];
    const int r = receivers[e];

    // ---- layer 1: [8] @ [8,64], scale 1/sqrt(8), silu -> sA ----
    {
        float4 ra = *(const float4*)(radial + (size_t)e * 8);
        float4 rb = *(const float4*)(radial + (size_t)e * 8 + 4);
        float rr[8] = { ra.x, ra.y, ra.z, ra.w, rb.x, rb.y, rb.z, rb.w };
        u64 acc[32];
#pragma unroll
        for (int j = 0; j < 32; j++) acc[j] = 0ull;
        const ulonglong2* Wv = (const ulonglong2*)sW1;
#pragma unroll
        for (int k = 0; k < 8; k++) {
            u64 a2 = pack2(rr[k], rr[k]);
            const ulonglong2* row = Wv + k * 16;
#pragma unroll
            for (int j = 0; j < 16; j++) {
                ulonglong2 w = row[j];
                acc[2 * j]     = fma2(a2, w.x, acc[2 * j]);
                acc[2 * j + 1] = fma2(a2, w.y, acc[2 * j + 1]);
            }
        }
        const float sc = 0.35355339059327373f;
#pragma unroll
        for (int j = 0; j < 32; j++) {
            float x, y; unpack2(acc[j], x, y);
            x *= sc; y *= sc;
            sA[(2 * j) * 257 + t]     = x / (1.f + __expf(-x));
            sA[(2 * j + 1) * 257 + t] = y / (1.f + __expf(-y));
        }
    }

    // ---- layers 2,3: 64->64, scale 1/8, silu ----
    layer64(sW2, sA, sB, t, 0.125f);
    layer64(sW3, sB, sA, t, 0.125f);

    // ---- spherical harmonics ----
    float y1v[3], y2v[5], one[1];
    {
        float vx = vectors[(size_t)e * 3 + 0];
        float vy = vectors[(size_t)e * 3 + 1];
        float vz = vectors[(size_t)e * 3 + 2];
        float rn = rsqrtf(vx * vx + vy * vy + vz * vz);
        float x = vx * rn, y = vy * rn, z = vz * rn;
        const float SQ3 = 1.7320508075688772f;
        const float S15 = 3.872983346207417f;
        y1v[0] = SQ3 * x; y1v[1] = SQ3 * y; y1v[2] = SQ3 * z;
        y2v[0] = S15 * x * y;
        y2v[1] = S15 * y * z;
        y2v[2] = 1.118033988749895f * (3.f * z * z - 1.f);
        y2v[3] = S15 * x * z;
        y2v[4] = 0.5f * S15 * (x * x - y * y);
        one[0] = 1.f;
    }

    // ---- layer 4 (3 segments of 64 cols) fused with message + vector-red scatter ----
    const float* hrow    = g_h   + (size_t)s * 64;
    float*       aggbase = g_agg + (size_t)r * 576;
    segment<0>(sW4, sA, t, hrow, aggbase, one);
    segment<1>(sW4, sA, t, hrow, aggbase, y1v);
    segment<2>(sW4, sA, t, hrow, aggbase, y2v);
}

// ---------------- kernel 4: down-projection (m-major reads, strided writes) ----
__global__ void __launch_bounds__(256) k_down(const float* __restrict__ w0,
                                              const float* __restrict__ w1,
                                              const float* __restrict__ w2,
                                              float* __restrict__ out) {
    __shared__ __align__(16) float sW[64 * 64];
    __shared__ float sA[64 * 65];

    const int seg = blockIdx.y;
    const float* W; int roff, woff, stride;
    if (seg == 0)      { W = w0; roff = 0;                 woff = 0;                stride = 1; }
    else if (seg < 4)  { W = w1; roff = 64  + (seg - 1) * 64; woff = 64  + (seg - 1); stride = 3; }
    else               { W = w2; roff = 256 + (seg - 4) * 64; woff = 256 + (seg - 4); stride = 5; }

    const int t  = threadIdx.x;
    const int nb = blockIdx.x * 64;

    for (int i = t; i < 4096; i += 256) sW[i] = W[i];
    for (int i = t; i < 4096; i += 256) {
        int rr = i >> 6, cc = i & 63;
        int n = nb + rr;
        sA[rr * 65 + cc] = (n < N_NODES) ? g_agg[(size_t)n * 576 + roff + cc] : 0.f;
    }
    __syncthreads();

    const int ty = t >> 4, tx = t & 15;
    const int r0 = ty * 4, d0 = tx * 4;
    float acc[4][4] = {};
#pragma unroll 8
    for (int k = 0; k < 64; k++) {
        float a[4];
#pragma unroll
        for (int i = 0; i < 4; i++) a[i] = sA[(r0 + i) * 65 + k];
        float4 b = *reinterpret_cast<const float4*>(&sW[k * 64 + d0]);
#pragma unroll
        for (int i = 0; i < 4; i++) {
            acc[i][0] += a[i] * b.x;
            acc[i][1] += a[i] * b.y;
            acc[i][2] += a[i] * b.z;
            acc[i][3] += a[i] * b.w;
        }
    }
#pragma unroll
    for (int i = 0; i < 4; i++) {
        int n = nb + r0 + i;
        if (n < N_NODES) {
#pragma unroll
            for (int j = 0; j < 4; j++)
                out[(size_t)n * 576 + woff + (size_t)(d0 + j) * stride] = acc[i][j] * 0.125f;
        }
    }
}

// ---------------- launcher ----------------------------------------------------
extern "C" void kernel_launch(void* const* d_in, const int* in_sizes, int n_in,
                              void* d_out, int out_size) {
    const float* vectors    = (const float*)d_in[0];
    const float* node_feats = (const float*)d_in[1];
    const float* radial     = (const float*)d_in[2];
    const int*   senders    = (const int*)  d_in[3];
    const int*   receivers  = (const int*)  d_in[4];
    const float* w_up       = (const float*)d_in[5];
    const float* mlp_w1     = (const float*)d_in[6];
    const float* mlp_w2     = (const float*)d_in[7];
    const float* mlp_w3     = (const float*)d_in[8];
    const float* mlp_w4     = (const float*)d_in[9];
    const float* w_down0    = (const float*)d_in[10];
    const float* w_down1    = (const float*)d_in[11];
    const float* w_down2    = (const float*)d_in[12];
    float* out = (float*)d_out;

    const int FUSED_SMEM = 53888 * 4;   // 215552 B
    cudaFuncSetAttribute(k_fused, cudaFuncAttributeMaxDynamicSharedMemorySize, FUSED_SMEM);

    k_zero<<<11250, 256>>>();
    k_node_up<<<625, 256>>>(node_feats, w_up);
    k_fused<<<1250, 256, FUSED_SMEM>>>(radial, vectors, senders, receivers,
                                       mlp_w1, mlp_w2, mlp_w3, mlp_w4);
    k_down<<<dim3(313, 9), 256>>>(w_down0, w_down1, w_down2, out);
}